// round 9
// baseline (speedup 1.0000x reference)
#include <cuda_runtime.h>
#include <cuda_fp16.h>
#include <math_constants.h>
#include <cstdint>

// ---------------------------------------------------------------- constants
#define NN 64
#define CC 3
#define NCC (NN*CC)        // 192 rows
#define LL 4096
#define KK 128             // shapelets
#define SS 64              // shapelet length
#define WW (LL - SS + 1)   // 4033 valid windows
#define GROUPS 4           // window groups per nc row
#define WPC 1024           // windows per CTA (16 tiles of 64)
#define TILES 16
#define GRID (NCC*GROUPS)  // 768 CTAs
#define TMAIN 256

#define STRIP 1096         // f32 strip elements (1024 + 64 + pad)
#define PSTR  546          // parity-pair words

// ---------------------------------------------------------------- scratch
__device__ uint32_t g_shp[CC*KK*32]; // shapelet fp16 pairs, row-major (32 u32 per k-row)
__device__ float    g_s2[CC*KK];     // ||s||^2
__device__ int      g_minb[NN*KK];   // running min d^2 (int bits)
__device__ int      g_ctr;           // completion counter (zero-init, self-reset)

__device__ __forceinline__ uint32_t packh(float a, float b) {
    __half2 h = __floats2half2_rn(a, b);   // low = a, high = b
    return *(uint32_t*)&h;
}

// ---------------------------------------------------------------- prep (tiny)
__global__ __launch_bounds__(256) void prep_kernel(const float* __restrict__ sh) {
    int t = blockIdx.x * blockDim.x + threadIdx.x;
    int nt = gridDim.x * blockDim.x;
    for (int i = t; i < CC * KK * 32; i += nt) {
        int base = (i >> 5) * SS + (i & 31) * 2;
        g_shp[i] = packh(sh[base], sh[base + 1]);
    }
    for (int i = t; i < CC * KK; i += nt) {
        const float* p = sh + i * SS;
        float s = 0.f;
#pragma unroll
        for (int j = 0; j < SS; j++) s = fmaf(p[j], p[j], s);
        g_s2[i] = s;
    }
    for (int i = t; i < NN * KK; i += nt) g_minb[i] = 0x7F800000;  // +inf
}

// ---------------------------------------------------------------- mma wrappers (f16 accum)
__device__ __forceinline__ void mma16816_h(uint32_t& c0, uint32_t& c1,
                                           uint32_t a0, uint32_t a1, uint32_t a2, uint32_t a3,
                                           uint32_t b0, uint32_t b1) {
    asm("mma.sync.aligned.m16n8k16.row.col.f16.f16.f16.f16 "
        "{%0,%1}, {%2,%3,%4,%5}, {%6,%7}, {%0,%1};"
        : "+r"(c0), "+r"(c1)
        : "r"(a0), "r"(a1), "r"(a2), "r"(a3), "r"(b0), "r"(b1));
}
// out-of-place with zero C
__device__ __forceinline__ void mma16816_hz(uint32_t& c0, uint32_t& c1,
                                            uint32_t a0, uint32_t a1, uint32_t a2, uint32_t a3,
                                            uint32_t b0, uint32_t b1) {
    uint32_t z = 0u;
    asm("mma.sync.aligned.m16n8k16.row.col.f16.f16.f16.f16 "
        "{%0,%1}, {%2,%3,%4,%5}, {%6,%7}, {%8,%8};"
        : "=r"(c0), "=r"(c1)
        : "r"(a0), "r"(a1), "r"(a2), "r"(a3), "r"(b0), "r"(b1), "r"(z));
}

__device__ __forceinline__ float2 h2f(uint32_t v) {
    return __half22float2(*(__half2*)&v);
}

// ---------------------------------------------------------------- main
// CTA = (nc row, group of 1024 windows = 16 tiles of 64).
// f16-accumulator HMMA; K=64 split into two independent f16 chains of K=32,
// combined in f32 in the epilogue (bounds accumulation error to ~1e-4 rel).
__global__ __launch_bounds__(TMAIN, 3) void main_kernel(const float* __restrict__ x,
                                                        float* __restrict__ out) {
    __shared__ float xs[STRIP];
    __shared__ uint32_t SE[PSTR], SO[PSTR];
    __shared__ float x2s[WPC];
    __shared__ uint32_t As[KK * 33];        // stride-33: conflict-free frag reads

    int b = blockIdx.x;
    int nc = b / GROUPS, grp = b % GROUPS;
    int c = nc % CC, n = nc / CC;
    int tid = threadIdx.x, lane = tid & 31, warp = tid >> 5;
    int wm = warp & 3, wn = warp >> 2;
    int q = lane & 3, g = lane >> 2;

    int ebase = grp * WPC;
    const float* xr = x + nc * LL;

    // 1) stage shapelet tile (channel c) into smem, coalesced
    {
        const uint32_t* src = g_shp + c * (KK * 32);
        for (int i = tid; i < KK * 32; i += TMAIN)
            As[(i >> 5) * 33 + (i & 31)] = src[i];
    }
    // 2) f32 strip (zero-padded past row end)
    for (int i = tid; i < STRIP; i += TMAIN) {
        int gidx = ebase + i;
        xs[i] = (gidx < LL) ? xr[gidx] : 0.f;
    }
    __syncthreads();

    // 3) fp16 parity packs
    for (int i = tid; i < PSTR; i += TMAIN) {
        float e0 = xs[2 * i], e1 = xs[2 * i + 1], e2 = xs[2 * i + 2];
        SE[i] = packh(e0, e1);
        SO[i] = packh(e1, e2);
    }
    // 4) window norms: 4 windows/thread via sliding update (near-exact)
    {
        int w0 = tid * 4;
        float s = 0.f;
#pragma unroll
        for (int i = 0; i < SS; i++) { float v = xs[w0 + i]; s = fmaf(v, v, s); }
        x2s[w0] = (ebase + w0 < WW) ? s : CUDART_INF_F;
#pragma unroll
        for (int r = 1; r < 4; r++) {
            int w = w0 + r;
            float vin = xs[w + SS - 1], vout = xs[w - 1];
            s = fmaf(vin, vin, fmaf(-vout, vout, s));
            x2s[w] = (ebase + w < WW) ? s : CUDART_INF_F;
        }
    }
    __syncthreads();

    // 5) A fragments: regs from smem (conflict-free), rows wm*32..wm*32+31
    uint32_t A[2][4][4];
    float s2v[2][2];
#pragma unroll
    for (int mt = 0; mt < 2; mt++) {
        int r0 = wm * 32 + mt * 16 + g;
        int r1 = r0 + 8;
        const uint32_t* ap0 = As + r0 * 33;
        const uint32_t* ap1 = As + r1 * 33;
#pragma unroll
        for (int ks = 0; ks < 4; ks++) {
            A[mt][ks][0] = ap0[ks * 8 + q];
            A[mt][ks][1] = ap1[ks * 8 + q];
            A[mt][ks][2] = ap0[ks * 8 + q + 4];
            A[mt][ks][3] = ap1[ks * 8 + q + 4];
        }
        s2v[mt][0] = g_s2[c * KK + r0];
        s2v[mt][1] = g_s2[c * KK + r1];
    }

    // per-lane strip pointer (parity of element index = g&1)
    const uint32_t* sp = ((g & 1) ? SO : SE) + (g >> 1) + q + wn * 16;
    int colbase = wn * 32 + q * 2;
    int tphase = 2 * warp;            // stagger: warps spread across 16 tiles

    float mn[2][2] = {{CUDART_INF_F, CUDART_INF_F}, {CUDART_INF_F, CUDART_INF_F}};

#pragma unroll 1
    for (int t0 = 0; t0 < TILES; t0++) {
        int t = (t0 + tphase) & (TILES - 1);

        // 11 distinct B words cover all (nt, ks) fragments of this tile
        uint32_t Bw[11];
#pragma unroll
        for (int j = 0; j < 11; j++) Bw[j] = sp[t * 32 + j * 4];

#pragma unroll
        for (int nt = 0; nt < 4; nt++) {
            // two independent f16 chains per mt: cA (ks 0-1), cB (ks 2-3)
            uint32_t cA0[2], cA1[2], cB0[2], cB1[2];
            mma16816_hz(cA0[0], cA0[1],
                        A[0][0][0], A[0][0][1], A[0][0][2], A[0][0][3],
                        Bw[nt], Bw[nt + 1]);
            mma16816_hz(cA1[0], cA1[1],
                        A[1][0][0], A[1][0][1], A[1][0][2], A[1][0][3],
                        Bw[nt], Bw[nt + 1]);
            mma16816_hz(cB0[0], cB0[1],
                        A[0][2][0], A[0][2][1], A[0][2][2], A[0][2][3],
                        Bw[nt + 4], Bw[nt + 5]);
            mma16816_hz(cB1[0], cB1[1],
                        A[1][2][0], A[1][2][1], A[1][2][2], A[1][2][3],
                        Bw[nt + 4], Bw[nt + 5]);
            mma16816_h(cA0[0], cA0[1],
                       A[0][1][0], A[0][1][1], A[0][1][2], A[0][1][3],
                       Bw[nt + 2], Bw[nt + 3]);
            mma16816_h(cA1[0], cA1[1],
                       A[1][1][0], A[1][1][1], A[1][1][2], A[1][1][3],
                       Bw[nt + 2], Bw[nt + 3]);
            mma16816_h(cB0[0], cB0[1],
                       A[0][3][0], A[0][3][1], A[0][3][2], A[0][3][3],
                       Bw[nt + 6], Bw[nt + 7]);
            mma16816_h(cB1[0], cB1[1],
                       A[1][3][0], A[1][3][1], A[1][3][2], A[1][3][3],
                       Bw[nt + 6], Bw[nt + 7]);

            // epilogue: combine chains in f32; min(x2[w] - 2*dot)
            float2 xv = *(const float2*)&x2s[t * 64 + colbase + nt * 8];
            {
                float2 a0 = h2f(cA0[0]), b0 = h2f(cB0[0]);   // rows g
                float2 a1 = h2f(cA0[1]), b1 = h2f(cB0[1]);   // rows g+8
                mn[0][0] = fminf(mn[0][0], fmaf(-2.f, a0.x + b0.x, xv.x));
                mn[0][0] = fminf(mn[0][0], fmaf(-2.f, a0.y + b0.y, xv.y));
                mn[0][1] = fminf(mn[0][1], fmaf(-2.f, a1.x + b1.x, xv.x));
                mn[0][1] = fminf(mn[0][1], fmaf(-2.f, a1.y + b1.y, xv.y));
            }
            {
                float2 a0 = h2f(cA1[0]), b0 = h2f(cB1[0]);
                float2 a1 = h2f(cA1[1]), b1 = h2f(cB1[1]);
                mn[1][0] = fminf(mn[1][0], fmaf(-2.f, a0.x + b0.x, xv.x));
                mn[1][0] = fminf(mn[1][0], fmaf(-2.f, a0.y + b0.y, xv.y));
                mn[1][1] = fminf(mn[1][1], fmaf(-2.f, a1.x + b1.x, xv.x));
                mn[1][1] = fminf(mn[1][1], fmaf(-2.f, a1.y + b1.y, xv.y));
            }
        }
    }

    // reduce over the 4 lanes sharing the same rows (same g, q = 0..3)
#pragma unroll
    for (int mt = 0; mt < 2; mt++)
#pragma unroll
        for (int h = 0; h < 2; h++) {
            float v = mn[mt][h];
            v = fminf(v, __shfl_xor_sync(0xFFFFFFFFu, v, 1));
            v = fminf(v, __shfl_xor_sync(0xFFFFFFFFu, v, 2));
            if (q == 0) {
                int row = wm * 32 + mt * 16 + h * 8 + g;
                atomicMin(&g_minb[n * KK + row], __float_as_int(v + s2v[mt][h]));
            }
        }

    // last CTA finalizes: sqrt(min d^2) -> out
    __shared__ int lastFlag;
    __threadfence();
    __syncthreads();
    if (tid == 0) lastFlag = (atomicAdd(&g_ctr, 1) == GRID - 1);
    __syncthreads();
    if (lastFlag) {
        __threadfence();
        for (int i = tid; i < NN * KK; i += TMAIN) {
            float d2 = __int_as_float(g_minb[i]);
            out[i] = sqrtf(fmaxf(d2, 0.f));
        }
        __threadfence();
        if (tid == 0) g_ctr = 0;
    }
}

// ---------------------------------------------------------------- launch
extern "C" void kernel_launch(void* const* d_in, const int* in_sizes, int n_in,
                              void* d_out, int out_size) {
    const float* x  = (const float*)d_in[0];
    const float* sh = (const float*)d_in[1];
    if (n_in >= 2 && in_sizes[0] == CC * KK * SS && in_sizes[1] == NN * CC * LL) {
        x  = (const float*)d_in[1];
        sh = (const float*)d_in[0];
    }
    prep_kernel<<<64, 256>>>(sh);
    main_kernel<<<GRID, TMAIN>>>(x, (float*)d_out);
}

// round 10
// speedup vs baseline: 1.1084x; 1.1084x over previous
#include <cuda_runtime.h>
#include <cuda_fp16.h>
#include <math_constants.h>
#include <cstdint>

// ---------------------------------------------------------------- constants
#define NN 64
#define CC 3
#define NCC (NN*CC)        // 192 rows
#define LL 4096
#define KK 128             // shapelets
#define SS 64              // shapelet length
#define WW (LL - SS + 1)   // 4033 valid windows
#define GROUPS 4           // window groups per nc row
#define WPC 1024           // windows per CTA (16 tiles of 64)
#define TILES 16
#define GRID (NCC*GROUPS)  // 768 CTAs
#define TMAIN 256

#define STRIP 1096         // f32 strip elements (1024 + 64 + pad)
#define PSTR  546          // parity-pair words

// ---------------------------------------------------------------- scratch
__device__ uint32_t g_shp[CC*KK*32]; // shapelet fp16 pairs, row-major (32 u32 per k-row)
__device__ float    g_s2[CC*KK];     // ||s||^2
__device__ int      g_minb[NN*KK];   // running min d^2 (int bits)
__device__ int      g_ctr;           // completion counter (zero-init, self-reset)

__device__ __forceinline__ uint32_t packh(float a, float b) {
    __half2 h = __floats2half2_rn(a, b);   // low = a, high = b
    return *(uint32_t*)&h;
}

// ---------------------------------------------------------------- prep (tiny)
__global__ __launch_bounds__(256) void prep_kernel(const float* __restrict__ sh) {
    int t = blockIdx.x * blockDim.x + threadIdx.x;
    int nt = gridDim.x * blockDim.x;
    for (int i = t; i < CC * KK * 32; i += nt) {
        int base = (i >> 5) * SS + (i & 31) * 2;
        g_shp[i] = packh(sh[base], sh[base + 1]);
    }
    for (int i = t; i < CC * KK; i += nt) {
        const float* p = sh + i * SS;
        float s = 0.f;
#pragma unroll
        for (int j = 0; j < SS; j++) s = fmaf(p[j], p[j], s);
        g_s2[i] = s;
    }
    for (int i = t; i < NN * KK; i += nt) g_minb[i] = 0x7F800000;  // +inf
}

// ---------------------------------------------------------------- mma wrappers (f16 accum)
__device__ __forceinline__ void mma16816_h(uint32_t& c0, uint32_t& c1,
                                           uint32_t a0, uint32_t a1, uint32_t a2, uint32_t a3,
                                           uint32_t b0, uint32_t b1) {
    asm("mma.sync.aligned.m16n8k16.row.col.f16.f16.f16.f16 "
        "{%0,%1}, {%2,%3,%4,%5}, {%6,%7}, {%0,%1};"
        : "+r"(c0), "+r"(c1)
        : "r"(a0), "r"(a1), "r"(a2), "r"(a3), "r"(b0), "r"(b1));
}
// out-of-place, C = {seed, seed} (both C regs share the same window columns)
__device__ __forceinline__ void mma16816_hs(uint32_t& c0, uint32_t& c1,
                                            uint32_t a0, uint32_t a1, uint32_t a2, uint32_t a3,
                                            uint32_t b0, uint32_t b1, uint32_t seed) {
    asm("mma.sync.aligned.m16n8k16.row.col.f16.f16.f16.f16 "
        "{%0,%1}, {%2,%3,%4,%5}, {%6,%7}, {%8,%8};"
        : "=r"(c0), "=r"(c1)
        : "r"(a0), "r"(a1), "r"(a2), "r"(a3), "r"(b0), "r"(b1), "r"(seed));
}

// ---------------------------------------------------------------- main
// CTA = (nc row, 1024 windows = 16 tiles of 64). f16-acc HMMA, K=64 as two
// independent K=32 chains; chain A's first MMA is C-seeded with -x2[w]/2 so
// the epilogue is just HADD2 (chain combine) + HMAX2 (running max).
// Final: d^2 = s2 - 2 * max(dot - x2/2).
__global__ __launch_bounds__(TMAIN, 3) void main_kernel(const float* __restrict__ x,
                                                        float* __restrict__ out) {
    __shared__ float xs[STRIP];
    __shared__ uint32_t SE[PSTR], SO[PSTR];
    __shared__ uint32_t negx2h[WPC / 2];    // packed {-x2/2} pairs (f16x2)
    __shared__ uint32_t As[KK * 33];        // stride-33: conflict-free frag reads

    int b = blockIdx.x;
    int nc = b / GROUPS, grp = b % GROUPS;
    int c = nc % CC, n = nc / CC;
    int tid = threadIdx.x, lane = tid & 31, warp = tid >> 5;
    int wm = warp & 3, wn = warp >> 2;
    int q = lane & 3, g = lane >> 2;

    int ebase = grp * WPC;
    const float* xr = x + nc * LL;

    // 1) stage shapelet tile (channel c) into smem, coalesced
    {
        const uint32_t* src = g_shp + c * (KK * 32);
        for (int i = tid; i < KK * 32; i += TMAIN)
            As[(i >> 5) * 33 + (i & 31)] = src[i];
    }
    // 2) f32 strip (zero-padded past row end)
    for (int i = tid; i < STRIP; i += TMAIN) {
        int gidx = ebase + i;
        xs[i] = (gidx < LL) ? xr[gidx] : 0.f;
    }
    __syncthreads();

    // 3) fp16 parity packs
    for (int i = tid; i < PSTR; i += TMAIN) {
        float e0 = xs[2 * i], e1 = xs[2 * i + 1], e2 = xs[2 * i + 2];
        SE[i] = packh(e0, e1);
        SO[i] = packh(e1, e2);
    }
    // 4) window norms: 4 windows/thread via sliding update; store -x2/2 as h2
    {
        int w0 = tid * 4;
        float v4[4];
        float s = 0.f;
#pragma unroll
        for (int i = 0; i < SS; i++) { float v = xs[w0 + i]; s = fmaf(v, v, s); }
        v4[0] = (ebase + w0 < WW) ? -0.5f * s : -CUDART_INF_F;
#pragma unroll
        for (int r = 1; r < 4; r++) {
            int w = w0 + r;
            float vin = xs[w + SS - 1], vout = xs[w - 1];
            s = fmaf(vin, vin, fmaf(-vout, vout, s));
            v4[r] = (ebase + w < WW) ? -0.5f * s : -CUDART_INF_F;
        }
        negx2h[w0 / 2]     = packh(v4[0], v4[1]);
        negx2h[w0 / 2 + 1] = packh(v4[2], v4[3]);
    }
    __syncthreads();

    // 5) A fragments: regs from smem (conflict-free), rows wm*32..wm*32+31
    uint32_t A[2][4][4];
    float s2v[2][2];
#pragma unroll
    for (int mt = 0; mt < 2; mt++) {
        int r0 = wm * 32 + mt * 16 + g;
        int r1 = r0 + 8;
        const uint32_t* ap0 = As + r0 * 33;
        const uint32_t* ap1 = As + r1 * 33;
#pragma unroll
        for (int ks = 0; ks < 4; ks++) {
            A[mt][ks][0] = ap0[ks * 8 + q];
            A[mt][ks][1] = ap1[ks * 8 + q];
            A[mt][ks][2] = ap0[ks * 8 + q + 4];
            A[mt][ks][3] = ap1[ks * 8 + q + 4];
        }
        s2v[mt][0] = g_s2[c * KK + r0];
        s2v[mt][1] = g_s2[c * KK + r1];
    }

    // per-lane strip pointer (parity of element index = g&1)
    const uint32_t* sp = ((g & 1) ? SO : SE) + (g >> 1) + q + wn * 16;
    // per-lane seed pointer: window-pair index = t*32 + wn*16 + q + nt*4
    const uint32_t* seedp = negx2h + wn * 16 + q;
    int tphase = 2 * warp;            // stagger: warps spread across 16 tiles

    const __half2 NEGINF2 = __half2half2(__float2half(-CUDART_INF_F));
    __half2 mn2[2][2] = {{NEGINF2, NEGINF2}, {NEGINF2, NEGINF2}};

#pragma unroll 1
    for (int t0 = 0; t0 < TILES; t0++) {
        int t = (t0 + tphase) & (TILES - 1);

        // 11 distinct B words cover all (nt, ks) fragments of this tile
        uint32_t Bw[11];
#pragma unroll
        for (int j = 0; j < 11; j++) Bw[j] = sp[t * 32 + j * 4];

#pragma unroll
        for (int nt = 0; nt < 4; nt++) {
            uint32_t seed = seedp[t * 32 + nt * 4];
            // chain A (ks 0-1) seeded with -x2/2; chain B (ks 2-3) seeded 0
            uint32_t cA0[2], cA1[2], cB0[2], cB1[2];
            mma16816_hs(cA0[0], cA0[1],
                        A[0][0][0], A[0][0][1], A[0][0][2], A[0][0][3],
                        Bw[nt], Bw[nt + 1], seed);
            mma16816_hs(cA1[0], cA1[1],
                        A[1][0][0], A[1][0][1], A[1][0][2], A[1][0][3],
                        Bw[nt], Bw[nt + 1], seed);
            mma16816_hs(cB0[0], cB0[1],
                        A[0][2][0], A[0][2][1], A[0][2][2], A[0][2][3],
                        Bw[nt + 4], Bw[nt + 5], 0u);
            mma16816_hs(cB1[0], cB1[1],
                        A[1][2][0], A[1][2][1], A[1][2][2], A[1][2][3],
                        Bw[nt + 4], Bw[nt + 5], 0u);
            mma16816_h(cA0[0], cA0[1],
                       A[0][1][0], A[0][1][1], A[0][1][2], A[0][1][3],
                       Bw[nt + 2], Bw[nt + 3]);
            mma16816_h(cA1[0], cA1[1],
                       A[1][1][0], A[1][1][1], A[1][1][2], A[1][1][3],
                       Bw[nt + 2], Bw[nt + 3]);
            mma16816_h(cB0[0], cB0[1],
                       A[0][3][0], A[0][3][1], A[0][3][2], A[0][3][3],
                       Bw[nt + 6], Bw[nt + 7]);
            mma16816_h(cB1[0], cB1[1],
                       A[1][3][0], A[1][3][1], A[1][3][2], A[1][3][3],
                       Bw[nt + 6], Bw[nt + 7]);

            // packed epilogue: combine chains, track running max (8 h2 ops)
            mn2[0][0] = __hmax2(mn2[0][0], __hadd2(*(__half2*)&cA0[0], *(__half2*)&cB0[0]));
            mn2[0][1] = __hmax2(mn2[0][1], __hadd2(*(__half2*)&cA0[1], *(__half2*)&cB0[1]));
            mn2[1][0] = __hmax2(mn2[1][0], __hadd2(*(__half2*)&cA1[0], *(__half2*)&cB1[0]));
            mn2[1][1] = __hmax2(mn2[1][1], __hadd2(*(__half2*)&cA1[1], *(__half2*)&cB1[1]));
        }
    }

    // reduce: max over h2 halves, then over the 4 q-lanes sharing rows
#pragma unroll
    for (int mt = 0; mt < 2; mt++)
#pragma unroll
        for (int h = 0; h < 2; h++) {
            float2 f = __half22float2(mn2[mt][h]);
            float m = fmaxf(f.x, f.y);
            m = fmaxf(m, __shfl_xor_sync(0xFFFFFFFFu, m, 1));
            m = fmaxf(m, __shfl_xor_sync(0xFFFFFFFFu, m, 2));
            if (q == 0) {
                int row = wm * 32 + mt * 16 + h * 8 + g;
                float d2 = fmaf(-2.f, m, s2v[mt][h]);
                atomicMin(&g_minb[n * KK + row], __float_as_int(d2));
            }
        }

    // last CTA finalizes: sqrt(min d^2) -> out
    __shared__ int lastFlag;
    __threadfence();
    __syncthreads();
    if (tid == 0) lastFlag = (atomicAdd(&g_ctr, 1) == GRID - 1);
    __syncthreads();
    if (lastFlag) {
        __threadfence();
        for (int i = tid; i < NN * KK; i += TMAIN) {
            float d2 = __int_as_float(g_minb[i]);
            out[i] = sqrtf(fmaxf(d2, 0.f));
        }
        __threadfence();
        if (tid == 0) g_ctr = 0;
    }
}

// ---------------------------------------------------------------- launch
extern "C" void kernel_launch(void* const* d_in, const int* in_sizes, int n_in,
                              void* d_out, int out_size) {
    const float* x  = (const float*)d_in[0];
    const float* sh = (const float*)d_in[1];
    if (n_in >= 2 && in_sizes[0] == CC * KK * SS && in_sizes[1] == NN * CC * LL) {
        x  = (const float*)d_in[1];
        sh = (const float*)d_in[0];
    }
    prep_kernel<<<64, 256>>>(sh);
    main_kernel<<<GRID, TMAIN>>>(x, (float*)d_out);
}

// round 11
// speedup vs baseline: 1.1299x; 1.0194x over previous
#include <cuda_runtime.h>
#include <cuda_fp16.h>
#include <math_constants.h>
#include <cstdint>

// ---------------------------------------------------------------- constants
#define NN 64
#define CC 3
#define NCC (NN*CC)        // 192 rows
#define LL 4096
#define KK 128             // shapelets
#define SS 64              // shapelet length
#define WW (LL - SS + 1)   // 4033 valid windows
#define TPR 64             // window tiles (of 64) per row
#define TTOT (NCC*TPR)     // 12288 tiles
#define GRID 296           // 2 CTAs x 148 SMs, single wave
#define TMAIN 256

#define MAXRUN 42          // max tiles per run (ceil(TTOT/GRID) = 42)
#define XSN 2768           // strip f32 (42*64+64 = 2752, + pad)
#define PSN 1392           // parity words (42*32+32 = 1376, + pad)
#define NGN 1344           // window pairs (42*32)

// ---------------------------------------------------------------- scratch
__device__ uint32_t g_shp[CC*KK*32]; // shapelet fp16 pairs, row-major
__device__ float    g_s2[CC*KK];     // ||s||^2
__device__ int      g_minb[NN*KK];   // running min d^2 (int bits)
__device__ int      g_ctr;           // completion counter (zero-init, self-reset)

__device__ __forceinline__ uint32_t packh(float a, float b) {
    __half2 h = __floats2half2_rn(a, b);
    return *(uint32_t*)&h;
}

// ---------------------------------------------------------------- prep (tiny)
__global__ __launch_bounds__(256) void prep_kernel(const float* __restrict__ sh) {
    int t = blockIdx.x * blockDim.x + threadIdx.x;
    int nt = gridDim.x * blockDim.x;
    for (int i = t; i < CC * KK * 32; i += nt) {
        int base = (i >> 5) * SS + (i & 31) * 2;
        g_shp[i] = packh(sh[base], sh[base + 1]);
    }
    for (int i = t; i < CC * KK; i += nt) {
        const float* p = sh + i * SS;
        float s = 0.f;
#pragma unroll
        for (int j = 0; j < SS; j++) s = fmaf(p[j], p[j], s);
        g_s2[i] = s;
    }
    for (int i = t; i < NN * KK; i += nt) g_minb[i] = 0x7F800000;  // +inf
}

// ---------------------------------------------------------------- mma wrappers (f16 accum)
__device__ __forceinline__ void mma16816_h(uint32_t& c0, uint32_t& c1,
                                           uint32_t a0, uint32_t a1, uint32_t a2, uint32_t a3,
                                           uint32_t b0, uint32_t b1) {
    asm("mma.sync.aligned.m16n8k16.row.col.f16.f16.f16.f16 "
        "{%0,%1}, {%2,%3,%4,%5}, {%6,%7}, {%0,%1};"
        : "+r"(c0), "+r"(c1)
        : "r"(a0), "r"(a1), "r"(a2), "r"(a3), "r"(b0), "r"(b1));
}
__device__ __forceinline__ void mma16816_hs(uint32_t& c0, uint32_t& c1,
                                            uint32_t a0, uint32_t a1, uint32_t a2, uint32_t a3,
                                            uint32_t b0, uint32_t b1, uint32_t seed) {
    asm("mma.sync.aligned.m16n8k16.row.col.f16.f16.f16.f16 "
        "{%0,%1}, {%2,%3,%4,%5}, {%6,%7}, {%8,%8};"
        : "=r"(c0), "=r"(c1)
        : "r"(a0), "r"(a1), "r"(a2), "r"(a3), "r"(b0), "r"(b1), "r"(seed));
}

// ---------------------------------------------------------------- main
// Persistent-style static split: 12288 tiles over 296 CTAs (runs of 41/42,
// <=1 row crossing per CTA). f16-acc HMMA, seeds carry -x2/2, epilogue =
// HADD2+HMAX2. Final: d^2 = s2 - 2*max(dot - x2/2).
__global__ __launch_bounds__(TMAIN, 2) void main_kernel(const float* __restrict__ x,
                                                        float* __restrict__ out) {
    __shared__ float xs[XSN];
    __shared__ uint32_t SE[PSN], SO[PSN];
    __shared__ uint32_t negx2h[NGN];
    __shared__ uint32_t As[KK * 33];

    int bi = blockIdx.x;
    int js = (int)(((long long)bi * TTOT) / GRID);
    int je = (int)(((long long)(bi + 1) * TTOT) / GRID);

    int tid = threadIdx.x, lane = tid & 31, warp = tid >> 5;
    int wm = warp & 3, wn = warp >> 2;
    int q = lane & 3, g = lane >> 2;

    while (js < je) {
        int row = js >> 6;                 // nc row
        int t0 = js & 63;
        int run = min(64 - t0, je - js);
        int c = row % CC, n = row / CC;
        int wbase = t0 * 64;               // first window of run within row
        int nelem = run * 64 + 64;
        int nW = run * 64;
        const float* xr = x + row * LL;

        __syncthreads();   // prior run's smem readers done

        // 1) stage shapelet tile (channel c), coalesced
        {
            const uint32_t* src = g_shp + c * (KK * 32);
            for (int i = tid; i < KK * 32; i += TMAIN)
                As[(i >> 5) * 33 + (i & 31)] = src[i];
        }
        // 2) f32 strip (zero-padded past row end)
        for (int i = tid; i < nelem + 8; i += TMAIN) {
            int gi = wbase + i;
            xs[i] = (gi < LL) ? xr[gi] : 0.f;
        }
        __syncthreads();

        // 3) fp16 parity packs
        {
            int np = run * 32 + 32;
            for (int i = tid; i < np; i += TMAIN) {
                float e0 = xs[2 * i], e1 = xs[2 * i + 1], e2 = xs[2 * i + 2];
                SE[i] = packh(e0, e1);
                SO[i] = packh(e1, e2);
            }
        }
        // 4) window norms (sliding update), stored as packed {-x2/2} f16 pairs
        {
            int ws = ((run + 7) >> 3) * 2;         // even windows/thread
            int w0 = tid * ws;
            if (w0 < nW) {
                float s = 0.f;
#pragma unroll
                for (int i = 0; i < SS; i++) { float v = xs[w0 + i]; s = fmaf(v, v, s); }
                float pv = (wbase + w0 < WW) ? -0.5f * s : -CUDART_INF_F;
                for (int r = 1; r < ws; r++) {
                    int w = w0 + r;
                    float vin = xs[w + SS - 1], vout = xs[w - 1];
                    s = fmaf(vin, vin, fmaf(-vout, vout, s));
                    float cv = (w < nW && wbase + w < WW) ? -0.5f * s : -CUDART_INF_F;
                    if (r & 1) negx2h[(w0 + r) >> 1] = packh(pv, cv);
                    pv = cv;
                }
            }
        }
        __syncthreads();

        // 5) A fragments + s2 (rows wm*32 .. wm*32+31)
        uint32_t A[2][4][4];
        float s2v[2][2];
#pragma unroll
        for (int mt = 0; mt < 2; mt++) {
            int r0 = wm * 32 + mt * 16 + g;
            int r1 = r0 + 8;
            const uint32_t* ap0 = As + r0 * 33;
            const uint32_t* ap1 = As + r1 * 33;
#pragma unroll
            for (int ks = 0; ks < 4; ks++) {
                A[mt][ks][0] = ap0[ks * 8 + q];
                A[mt][ks][1] = ap1[ks * 8 + q];
                A[mt][ks][2] = ap0[ks * 8 + q + 4];
                A[mt][ks][3] = ap1[ks * 8 + q + 4];
            }
            s2v[mt][0] = g_s2[c * KK + r0];
            s2v[mt][1] = g_s2[c * KK + r1];
        }

        const uint32_t* sp = ((g & 1) ? SO : SE) + (g >> 1) + q + wn * 16;
        const uint32_t* seedp = negx2h + wn * 16 + q;

        const __half2 NEGINF2 = __half2half2(__float2half(-CUDART_INF_F));
        __half2 mn2[2][2] = {{NEGINF2, NEGINF2}, {NEGINF2, NEGINF2}};

        // prime B words for tile 0
        uint32_t Bw[11];
#pragma unroll
        for (int j = 0; j < 11; j++) Bw[j] = sp[j * 4];

#pragma unroll 1
        for (int t = 0; t < run; t++) {
            uint32_t Bn[11];
            bool more = (t + 1 < run);
#pragma unroll
            for (int j = 0; j < 11; j++) Bn[j] = more ? sp[32 + j * 4] : 0u;

#pragma unroll
            for (int nt = 0; nt < 4; nt++) {
                uint32_t seed = seedp[nt * 4];
                uint32_t cA0[2], cA1[2], cB0[2], cB1[2];
                mma16816_hs(cA0[0], cA0[1],
                            A[0][0][0], A[0][0][1], A[0][0][2], A[0][0][3],
                            Bw[nt], Bw[nt + 1], seed);
                mma16816_hs(cA1[0], cA1[1],
                            A[1][0][0], A[1][0][1], A[1][0][2], A[1][0][3],
                            Bw[nt], Bw[nt + 1], seed);
                mma16816_hs(cB0[0], cB0[1],
                            A[0][2][0], A[0][2][1], A[0][2][2], A[0][2][3],
                            Bw[nt + 4], Bw[nt + 5], 0u);
                mma16816_hs(cB1[0], cB1[1],
                            A[1][2][0], A[1][2][1], A[1][2][2], A[1][2][3],
                            Bw[nt + 4], Bw[nt + 5], 0u);
                mma16816_h(cA0[0], cA0[1],
                           A[0][1][0], A[0][1][1], A[0][1][2], A[0][1][3],
                           Bw[nt + 2], Bw[nt + 3]);
                mma16816_h(cA1[0], cA1[1],
                           A[1][1][0], A[1][1][1], A[1][1][2], A[1][1][3],
                           Bw[nt + 2], Bw[nt + 3]);
                mma16816_h(cB0[0], cB0[1],
                           A[0][3][0], A[0][3][1], A[0][3][2], A[0][3][3],
                           Bw[nt + 6], Bw[nt + 7]);
                mma16816_h(cB1[0], cB1[1],
                           A[1][3][0], A[1][3][1], A[1][3][2], A[1][3][3],
                           Bw[nt + 6], Bw[nt + 7]);

                mn2[0][0] = __hmax2(mn2[0][0], __hadd2(*(__half2*)&cA0[0], *(__half2*)&cB0[0]));
                mn2[0][1] = __hmax2(mn2[0][1], __hadd2(*(__half2*)&cA0[1], *(__half2*)&cB0[1]));
                mn2[1][0] = __hmax2(mn2[1][0], __hadd2(*(__half2*)&cA1[0], *(__half2*)&cB1[0]));
                mn2[1][1] = __hmax2(mn2[1][1], __hadd2(*(__half2*)&cA1[1], *(__half2*)&cB1[1]));
            }
#pragma unroll
            for (int j = 0; j < 11; j++) Bw[j] = Bn[j];
            sp += 32;
            seedp += 32;
        }

        // reduce: max over h2 halves, then over the 4 q-lanes sharing rows
#pragma unroll
        for (int mt = 0; mt < 2; mt++)
#pragma unroll
            for (int h = 0; h < 2; h++) {
                float2 f = __half22float2(mn2[mt][h]);
                float m = fmaxf(f.x, f.y);
                m = fmaxf(m, __shfl_xor_sync(0xFFFFFFFFu, m, 1));
                m = fmaxf(m, __shfl_xor_sync(0xFFFFFFFFu, m, 2));
                if (q == 0) {
                    int kr = wm * 32 + mt * 16 + h * 8 + g;
                    float d2 = fmaf(-2.f, m, s2v[mt][h]);
                    atomicMin(&g_minb[n * KK + kr], __float_as_int(d2));
                }
            }

        js += run;
    }

    // last CTA finalizes: sqrt(min d^2) -> out
    __shared__ int lastFlag;
    __threadfence();
    __syncthreads();
    if (tid == 0) lastFlag = (atomicAdd(&g_ctr, 1) == GRID - 1);
    __syncthreads();
    if (lastFlag) {
        __threadfence();
        for (int i = tid; i < NN * KK; i += TMAIN) {
            float d2 = __int_as_float(g_minb[i]);
            out[i] = sqrtf(fmaxf(d2, 0.f));
        }
        __threadfence();
        if (tid == 0) g_ctr = 0;
    }
}

// ---------------------------------------------------------------- launch
extern "C" void kernel_launch(void* const* d_in, const int* in_sizes, int n_in,
                              void* d_out, int out_size) {
    const float* x  = (const float*)d_in[0];
    const float* sh = (const float*)d_in[1];
    if (n_in >= 2 && in_sizes[0] == CC * KK * SS && in_sizes[1] == NN * CC * LL) {
        x  = (const float*)d_in[1];
        sh = (const float*)d_in[0];
    }
    prep_kernel<<<64, 256>>>(sh);
    main_kernel<<<GRID, TMAIN>>>(x, (float*)d_out);
}

// round 12
// speedup vs baseline: 1.1683x; 1.0340x over previous
#include <cuda_runtime.h>
#include <cuda_fp16.h>
#include <math_constants.h>
#include <cstdint>

// ---------------------------------------------------------------- constants
#define NN 64
#define CC 3
#define NCC (NN*CC)        // 192 rows
#define LL 4096
#define KK 128             // shapelets
#define SS 64              // shapelet length
#define WW (LL - SS + 1)   // 4033 valid windows
#define TPR 64             // window tiles (of 64) per row
#define TTOT (NCC*TPR)     // 12288 tiles
#define GRID 296           // 2 CTAs x 148 SMs, single wave
#define TMAIN 256

#define XSN 2768           // strip f32 (42*64+64, + pad)
#define PSN 1472           // parity words (42*32+32, + prefetch overrun pad)
#define NGN 1440           // window pairs (42*32, + prefetch overrun pad)

// ---------------------------------------------------------------- scratch
__device__ uint32_t g_shp[CC*KK*32]; // shapelet fp16 pairs, row-major
__device__ float    g_s2[CC*KK];     // ||s||^2
__device__ int      g_minb[NN*KK];   // running min d^2 (int bits)
__device__ int      g_ctr;           // completion counter (zero-init, self-reset)

__device__ __forceinline__ uint32_t packh(float a, float b) {
    __half2 h = __floats2half2_rn(a, b);
    return *(uint32_t*)&h;
}

// ---------------------------------------------------------------- prep (tiny)
__global__ __launch_bounds__(256) void prep_kernel(const float* __restrict__ sh) {
    int t = blockIdx.x * blockDim.x + threadIdx.x;
    int nt = gridDim.x * blockDim.x;
    for (int i = t; i < CC * KK * 32; i += nt) {
        int base = (i >> 5) * SS + (i & 31) * 2;
        g_shp[i] = packh(sh[base], sh[base + 1]);
    }
    for (int i = t; i < CC * KK; i += nt) {
        const float* p = sh + i * SS;
        float s = 0.f;
#pragma unroll
        for (int j = 0; j < SS; j++) s = fmaf(p[j], p[j], s);
        g_s2[i] = s;
    }
    for (int i = t; i < NN * KK; i += nt) g_minb[i] = 0x7F800000;  // +inf
}

// ---------------------------------------------------------------- mma wrappers (f16 accum)
__device__ __forceinline__ void mma16816_h(uint32_t& c0, uint32_t& c1,
                                           uint32_t a0, uint32_t a1, uint32_t a2, uint32_t a3,
                                           uint32_t b0, uint32_t b1) {
    asm("mma.sync.aligned.m16n8k16.row.col.f16.f16.f16.f16 "
        "{%0,%1}, {%2,%3,%4,%5}, {%6,%7}, {%0,%1};"
        : "+r"(c0), "+r"(c1)
        : "r"(a0), "r"(a1), "r"(a2), "r"(a3), "r"(b0), "r"(b1));
}
__device__ __forceinline__ void mma16816_hs(uint32_t& c0, uint32_t& c1,
                                            uint32_t a0, uint32_t a1, uint32_t a2, uint32_t a3,
                                            uint32_t b0, uint32_t b1, uint32_t seed) {
    asm("mma.sync.aligned.m16n8k16.row.col.f16.f16.f16.f16 "
        "{%0,%1}, {%2,%3,%4,%5}, {%6,%7}, {%8,%8};"
        : "=r"(c0), "=r"(c1)
        : "r"(a0), "r"(a1), "r"(a2), "r"(a3), "r"(b0), "r"(b1), "r"(seed));
}

// ---------------------------------------------------------------- main
// Persistent static split (12288 tiles over 296 CTAs). f16-acc HMMA; one
// serial K-chain of 4 MMAs per (mt,nt) seeded with -x2/2 (ks-outer order ->
// 8 independent chains, RAW hidden). Whole-tile burst, then prefetch next
// tile's B+seeds, then a single 8xHMAX2 epilogue.
// Final: d^2 = s2 - 2*max(dot - x2/2).
__global__ __launch_bounds__(TMAIN, 2) void main_kernel(const float* __restrict__ x,
                                                        float* __restrict__ out) {
    __shared__ float xs[XSN];
    __shared__ uint32_t SE[PSN], SO[PSN];
    __shared__ uint32_t negx2h[NGN];
    __shared__ uint32_t As[KK * 33];

    int bi = blockIdx.x;
    int js = (int)(((long long)bi * TTOT) / GRID);
    int je = (int)(((long long)(bi + 1) * TTOT) / GRID);

    int tid = threadIdx.x, lane = tid & 31, warp = tid >> 5;
    int wm = warp & 3, wn = warp >> 2;
    int q = lane & 3, g = lane >> 2;

    while (js < je) {
        int row = js >> 6;                 // nc row
        int t0 = js & 63;
        int run = min(64 - t0, je - js);
        int c = row % CC, n = row / CC;
        int wbase = t0 * 64;               // first window of run within row
        int nelem = run * 64 + 64;
        int nW = run * 64;
        const float* xr = x + row * LL;

        __syncthreads();   // prior run's smem readers done

        // 1) stage shapelet tile (channel c), coalesced
        {
            const uint32_t* src = g_shp + c * (KK * 32);
            for (int i = tid; i < KK * 32; i += TMAIN)
                As[(i >> 5) * 33 + (i & 31)] = src[i];
        }
        // 2) f32 strip (zero-padded past row end)
        for (int i = tid; i < nelem + 8; i += TMAIN) {
            int gi = wbase + i;
            xs[i] = (gi < LL) ? xr[gi] : 0.f;
        }
        __syncthreads();

        // 3) fp16 parity packs (pad region up to PSN zeroed for prefetch reads)
        {
            int np = run * 32 + 32;
            for (int i = tid; i < np; i += TMAIN) {
                float e0 = xs[2 * i], e1 = xs[2 * i + 1], e2 = xs[2 * i + 2];
                SE[i] = packh(e0, e1);
                SO[i] = packh(e1, e2);
            }
            for (int i = np + tid; i < PSN; i += TMAIN) { SE[i] = 0u; SO[i] = 0u; }
            for (int i = run * 32 + tid; i < NGN; i += TMAIN) negx2h[i] = 0u;
        }
        // 4) window norms (sliding update), stored as packed {-x2/2} f16 pairs
        {
            int ws = ((run + 7) >> 3) * 2;         // even windows/thread
            int w0 = tid * ws;
            if (w0 < nW) {
                float s = 0.f;
#pragma unroll
                for (int i = 0; i < SS; i++) { float v = xs[w0 + i]; s = fmaf(v, v, s); }
                float pv = (wbase + w0 < WW) ? -0.5f * s : -CUDART_INF_F;
                for (int r = 1; r < ws; r++) {
                    int w = w0 + r;
                    float vin = xs[w + SS - 1], vout = xs[w - 1];
                    s = fmaf(vin, vin, fmaf(-vout, vout, s));
                    float cv = (w < nW && wbase + w < WW) ? -0.5f * s : -CUDART_INF_F;
                    if (r & 1) negx2h[(w0 + r) >> 1] = packh(pv, cv);
                    pv = cv;
                }
            }
        }
        __syncthreads();

        // 5) A fragments + s2 (rows wm*32 .. wm*32+31)
        uint32_t A[2][4][4];
        float s2v[2][2];
#pragma unroll
        for (int mt = 0; mt < 2; mt++) {
            int r0 = wm * 32 + mt * 16 + g;
            int r1 = r0 + 8;
            const uint32_t* ap0 = As + r0 * 33;
            const uint32_t* ap1 = As + r1 * 33;
#pragma unroll
            for (int ks = 0; ks < 4; ks++) {
                A[mt][ks][0] = ap0[ks * 8 + q];
                A[mt][ks][1] = ap1[ks * 8 + q];
                A[mt][ks][2] = ap0[ks * 8 + q + 4];
                A[mt][ks][3] = ap1[ks * 8 + q + 4];
            }
            s2v[mt][0] = g_s2[c * KK + r0];
            s2v[mt][1] = g_s2[c * KK + r1];
        }

        const uint32_t* sp = ((g & 1) ? SO : SE) + (g >> 1) + q + wn * 16;
        const uint32_t* seedp = negx2h + wn * 16 + q;

        const __half2 NEGINF2 = __half2half2(__float2half(-CUDART_INF_F));
        __half2 mn2[2][2] = {{NEGINF2, NEGINF2}, {NEGINF2, NEGINF2}};

        // prime B words + seeds for tile 0
        uint32_t Bw[11], Sd[4];
#pragma unroll
        for (int j = 0; j < 11; j++) Bw[j] = sp[j * 4];
#pragma unroll
        for (int j = 0; j < 4; j++) Sd[j] = seedp[j * 4];

#pragma unroll 1
        for (int t = 0; t < run; t++) {
            uint32_t C[2][4][2];   // [mt][nt][half] -- 8 serial K-chains

            // ks = 0: seed with -x2/2
#pragma unroll
            for (int nt = 0; nt < 4; nt++) {
                mma16816_hs(C[0][nt][0], C[0][nt][1],
                            A[0][0][0], A[0][0][1], A[0][0][2], A[0][0][3],
                            Bw[nt], Bw[nt + 1], Sd[nt]);
                mma16816_hs(C[1][nt][0], C[1][nt][1],
                            A[1][0][0], A[1][0][1], A[1][0][2], A[1][0][3],
                            Bw[nt], Bw[nt + 1], Sd[nt]);
            }
            // ks = 1..3 accumulate into the same chains (ks-outer: ILP = 8)
#pragma unroll
            for (int ks = 1; ks < 4; ks++)
#pragma unroll
                for (int nt = 0; nt < 4; nt++) {
                    mma16816_h(C[0][nt][0], C[0][nt][1],
                               A[0][ks][0], A[0][ks][1], A[0][ks][2], A[0][ks][3],
                               Bw[nt + 2 * ks], Bw[nt + 2 * ks + 1]);
                    mma16816_h(C[1][nt][0], C[1][nt][1],
                               A[1][ks][0], A[1][ks][1], A[1][ks][2], A[1][ks][3],
                               Bw[nt + 2 * ks], Bw[nt + 2 * ks + 1]);
                }

            // prefetch next tile's B words + seeds (overlaps HMMA drain)
#pragma unroll
            for (int j = 0; j < 11; j++) Bw[j] = sp[32 + j * 4];
#pragma unroll
            for (int j = 0; j < 4; j++) Sd[j] = seedp[32 + j * 4];
            sp += 32;
            seedp += 32;

            // single epilogue: 8 HMAX2
#pragma unroll
            for (int nt = 0; nt < 4; nt++) {
                mn2[0][0] = __hmax2(mn2[0][0], *(__half2*)&C[0][nt][0]);
                mn2[0][1] = __hmax2(mn2[0][1], *(__half2*)&C[0][nt][1]);
                mn2[1][0] = __hmax2(mn2[1][0], *(__half2*)&C[1][nt][0]);
                mn2[1][1] = __hmax2(mn2[1][1], *(__half2*)&C[1][nt][1]);
            }
        }

        // reduce: max over h2 halves, then over the 4 q-lanes sharing rows
#pragma unroll
        for (int mt = 0; mt < 2; mt++)
#pragma unroll
            for (int h = 0; h < 2; h++) {
                float2 f = __half22float2(mn2[mt][h]);
                float m = fmaxf(f.x, f.y);
                m = fmaxf(m, __shfl_xor_sync(0xFFFFFFFFu, m, 1));
                m = fmaxf(m, __shfl_xor_sync(0xFFFFFFFFu, m, 2));
                if (q == 0) {
                    int kr = wm * 32 + mt * 16 + h * 8 + g;
                    float d2 = fmaf(-2.f, m, s2v[mt][h]);
                    atomicMin(&g_minb[n * KK + kr], __float_as_int(d2));
                }
            }

        js += run;
    }

    // last CTA finalizes: sqrt(min d^2) -> out
    __shared__ int lastFlag;
    __threadfence();
    __syncthreads();
    if (tid == 0) lastFlag = (atomicAdd(&g_ctr, 1) == GRID - 1);
    __syncthreads();
    if (lastFlag) {
        __threadfence();
        for (int i = tid; i < NN * KK; i += TMAIN) {
            float d2 = __int_as_float(g_minb[i]);
            out[i] = sqrtf(fmaxf(d2, 0.f));
        }
        __threadfence();
        if (tid == 0) g_ctr = 0;
    }
}

// ---------------------------------------------------------------- launch
extern "C" void kernel_launch(void* const* d_in, const int* in_sizes, int n_in,
                              void* d_out, int out_size) {
    const float* x  = (const float*)d_in[0];
    const float* sh = (const float*)d_in[1];
    if (n_in >= 2 && in_sizes[0] == CC * KK * SS && in_sizes[1] == NN * CC * LL) {
        x  = (const float*)d_in[1];
        sh = (const float*)d_in[0];
    }
    prep_kernel<<<64, 256>>>(sh);
    main_kernel<<<GRID, TMAIN>>>(x, (float*)d_out);
}